// round 15
// baseline (speedup 1.0000x reference)
#include <cuda_runtime.h>
#include <cstdint>

typedef unsigned long long ull;

#define B_   4
#define S_   2048
#define DM_  2048
#define DS_  64
#define REC_ 336
// record: q[0:64] k[64:128] a[128:192] km[192:256] v[256:320]
// scalars: [320]g1A [321]g1C [322]c [323]g1Y [324]g2A [325]g2C [326]g2Y
//          [327]g3A [328]g3C [329]g3Y

__device__ __forceinline__ ull fma2(ull a, ull b, ull c) {
    ull d; asm("fma.rn.f32x2 %0,%1,%2,%3;" : "=l"(d) : "l"(a), "l"(b), "l"(c)); return d;
}
__device__ __forceinline__ ull mul2(ull a, ull b) {
    ull d; asm("mul.rn.f32x2 %0,%1,%2;" : "=l"(d) : "l"(a), "l"(b)); return d;
}
__device__ __forceinline__ ull pack2(float lo, float hi) {
    ull d; asm("mov.b64 %0, {%1,%2};" : "=l"(d) : "f"(lo), "f"(hi)); return d;
}
__device__ __forceinline__ float2 unpack2(ull a) {
    float lo, hi; asm("mov.b64 {%0,%1}, %2;" : "=f"(lo), "=f"(hi) : "l"(a));
    return make_float2(lo, hi);
}
__device__ __forceinline__ void cp_async16(void* smem, const void* gmem) {
    uint32_t s = (uint32_t)__cvta_generic_to_shared(smem);
    asm volatile("cp.async.cg.shared.global [%0], [%1], 16;" :: "r"(s), "l"(gmem) : "memory");
}
#define CP_COMMIT()  asm volatile("cp.async.commit_group;" ::: "memory")
#define CP_WAIT1()   asm volatile("cp.async.wait_group 1;" ::: "memory")
#define BAR0()       asm volatile("bar.sync 0;" ::: "memory")

__device__ float g_raw[B_ * S_ * 256];
__device__ float g_inp[B_ * S_ * REC_];
__device__ float g_y  [B_ * S_ * DS_];

// =====================================================================
// Kernel A: projection GEMM (proven)
// =====================================================================
#define BM 64
#define BN 64
#define BK 32

__global__ void __launch_bounds__(256) proj_gemm(
    const float* __restrict__ x,
    const float* __restrict__ Wk, const float* __restrict__ Wv,
    const float* __restrict__ Wq, const float* __restrict__ Wa)
{
    __shared__ __align__(16) float As[BK][BM + 4];
    __shared__ __align__(16) float Bs[BK][BN + 4];

    const int mt = blockIdx.x;
    const int nt = blockIdx.y;
    const float* W = (nt == 0) ? Wk : (nt == 1) ? Wv : (nt == 2) ? Wq : Wa;

    const int tid  = threadIdx.x;
    const int lrow = tid >> 2;
    const int lk   = (tid & 3) * 4;
    const float* xg = x + (size_t)(mt * BM + lrow) * DM_ + lk;
    const float* wg = W + (size_t)lrow * DM_ + lk;

    const int tn4 = (tid & 15) * 4;
    const int tm4 = (tid >> 4) * 4;

    ull acc[4][2];
    #pragma unroll
    for (int i = 0; i < 4; i++) { acc[i][0] = 0ull; acc[i][1] = 0ull; }

    float4 av0 = *(const float4*)xg;
    float4 av1 = *(const float4*)(xg + 16);
    float4 bv0 = *(const float4*)wg;
    float4 bv1 = *(const float4*)(wg + 16);

    for (int k0 = 0; k0 < DM_; k0 += BK) {
        __syncthreads();
        As[lk + 0][lrow] = av0.x; As[lk + 1][lrow] = av0.y;
        As[lk + 2][lrow] = av0.z; As[lk + 3][lrow] = av0.w;
        As[lk + 16][lrow] = av1.x; As[lk + 17][lrow] = av1.y;
        As[lk + 18][lrow] = av1.z; As[lk + 19][lrow] = av1.w;
        Bs[lk + 0][lrow] = bv0.x; Bs[lk + 1][lrow] = bv0.y;
        Bs[lk + 2][lrow] = bv0.z; Bs[lk + 3][lrow] = bv0.w;
        Bs[lk + 16][lrow] = bv1.x; Bs[lk + 17][lrow] = bv1.y;
        Bs[lk + 18][lrow] = bv1.z; Bs[lk + 19][lrow] = bv1.w;
        if (k0 + BK < DM_) {
            av0 = *(const float4*)(xg + k0 + BK);
            av1 = *(const float4*)(xg + k0 + BK + 16);
            bv0 = *(const float4*)(wg + k0 + BK);
            bv1 = *(const float4*)(wg + k0 + BK + 16);
        }
        __syncthreads();
        #pragma unroll
        for (int kk = 0; kk < BK; kk++) {
            ulonglong2 bb = *(const ulonglong2*)&Bs[kk][tn4];
            float4 a4 = *(const float4*)&As[kk][tm4];
            ull p0 = pack2(a4.x, a4.x), p1 = pack2(a4.y, a4.y);
            ull p2 = pack2(a4.z, a4.z), p3 = pack2(a4.w, a4.w);
            acc[0][0] = fma2(p0, bb.x, acc[0][0]); acc[0][1] = fma2(p0, bb.y, acc[0][1]);
            acc[1][0] = fma2(p1, bb.x, acc[1][0]); acc[1][1] = fma2(p1, bb.y, acc[1][1]);
            acc[2][0] = fma2(p2, bb.x, acc[2][0]); acc[2][1] = fma2(p2, bb.y, acc[2][1]);
            acc[3][0] = fma2(p3, bb.x, acc[3][0]); acc[3][1] = fma2(p3, bb.y, acc[3][1]);
        }
    }

    #pragma unroll
    for (int i = 0; i < 4; i++) {
        int m = mt * BM + tm4 + i;
        #pragma unroll
        for (int j = 0; j < 2; j++) {
            float2 f = unpack2(acc[i][j]);
            *(float2*)&g_raw[(size_t)m * 256 + nt * 64 + tn4 + 2 * j] = f;
        }
    }
}

// =====================================================================
// Kernel B: per-token prep (proven)
// =====================================================================
__global__ void __launch_bounds__(256) prep_kernel(
    const float* __restrict__ Wa_b, const float* __restrict__ lam)
{
    const int g    = blockIdx.x * 8 + (threadIdx.x >> 5);
    const int lane = threadIdx.x & 31;
    const float* r_ = g_raw + (size_t)g * 256;

    float k0 = r_[lane],        k1 = r_[lane + 32];
    float v0 = r_[64 + lane],   v1 = r_[96 + lane];
    float q0 = r_[128 + lane],  q1 = r_[160 + lane];
    float z0 = r_[192 + lane] + Wa_b[lane];
    float z1 = r_[224 + lane] + Wa_b[lane + 32];

    float kn = k0 * k0 + k1 * k1;
    #pragma unroll
    for (int m = 1; m < 32; m <<= 1) kn += __shfl_xor_sync(~0u, kn, m);
    float kinv = 1.0f / fmaxf(sqrtf(kn), 1e-12f);
    k0 *= kinv; k1 *= kinv;

    float qn = q0 * q0 + q1 * q1;
    #pragma unroll
    for (int m = 1; m < 32; m <<= 1) qn += __shfl_xor_sync(~0u, qn, m);
    float qinv = 1.0f / fmaxf(sqrtf(qn), 1e-12f);
    q0 *= qinv; q1 *= qinv;

    float la0 = logf(1.0f / (1.0f + expf(-lam[lane])) + 1e-8f);
    float la1 = logf(1.0f / (1.0f + expf(-lam[lane + 32])) + 1e-8f);
    float rr0 = 1.0f / (1.0f + expf(-z0));
    float rr1 = 1.0f / (1.0f + expf(-z1));
    float al0 = expf(8.0f * rr0 * la0);
    float al1 = expf(8.0f * rr1 * la1);
    float km0 = k0 * (1.0f - al0), km1 = k1 * (1.0f - al1);

    float c = q0 * km0 + q1 * km1;
    #pragma unroll
    for (int m = 1; m < 32; m <<= 1) c += __shfl_xor_sync(~0u, c, m);

    float* o = g_inp + (size_t)g * REC_;
    o[lane] = q0;          o[lane + 32] = q1;
    o[64 + lane] = k0;     o[96 + lane] = k1;
    o[128 + lane] = al0;   o[160 + lane] = al1;
    o[192 + lane] = km0;   o[224 + lane] = km1;
    o[256 + lane] = v0;    o[288 + lane] = v1;
    if (lane == 0) o[322] = c;
}

// =====================================================================
// Kernel B2: lag-1/2/3 scalars. m1=km', m2=a'(.)km'', m3=a'a''(.)km'''
// =====================================================================
__global__ void __launch_bounds__(256) ghc_kernel()
{
    const int g    = blockIdx.x * 8 + (threadIdx.x >> 5);
    const int lane = threadIdx.x & 31;
    const int t    = g & (S_ - 1);
    float* cur = g_inp + (size_t)g * REC_;
    const float* p1 = cur - REC_;
    const float* p2 = cur - 2 * REC_;
    const float* p3 = cur - 3 * REC_;

    float m10 = 0.f, m11 = 0.f, m20 = 0.f, m21 = 0.f, m30 = 0.f, m31 = 0.f;
    if (t >= 1) { m10 = p1[192 + lane]; m11 = p1[224 + lane]; }
    if (t >= 2) {
        float a10 = p1[128 + lane], a11 = p1[160 + lane];
        m20 = a10 * p2[192 + lane]; m21 = a11 * p2[224 + lane];
        if (t >= 3) {
            m30 = a10 * p2[128 + lane] * p3[192 + lane];
            m31 = a11 * p2[160 + lane] * p3[224 + lane];
        }
    }
    float q0 = cur[lane], q1 = cur[lane + 32];
    float k0 = cur[64 + lane], k1 = cur[96 + lane];
    float a0 = cur[128 + lane], a1 = cur[160 + lane];
    float y0 = q0 * a0, y1 = q1 * a1;

    float vv[9];
    vv[0] = q0*m10 + q1*m11; vv[1] = k0*m10 + k1*m11; vv[2] = y0*m10 + y1*m11;
    vv[3] = q0*m20 + q1*m21; vv[4] = k0*m20 + k1*m21; vv[5] = y0*m20 + y1*m21;
    vv[6] = q0*m30 + q1*m31; vv[7] = k0*m30 + k1*m31; vv[8] = y0*m30 + y1*m31;
    #pragma unroll
    for (int x = 0; x < 9; x++)
        #pragma unroll
        for (int m = 1; m < 32; m <<= 1) vv[x] += __shfl_xor_sync(~0u, vv[x], m);

    if (lane == 0) {
        cur[320] = vv[0]; cur[321] = vv[1]; cur[323] = vv[2];
        cur[324] = vv[3]; cur[325] = vv[4]; cur[326] = vv[5];
        cur[327] = vv[6]; cur[328] = vv[7]; cur[329] = vv[8];
    }
}

// =====================================================================
// Kernel C: 2-token-epoch warp-specialized scan. 4 CTAs x 288 threads.
// Warps 0-7 vector (2v x 8k), warp 8 sequencer. ONE bar.sync per 2 steps.
// 8-slot STATIC ring; km/a carried in registers across epochs.
// =====================================================================
__device__ __forceinline__ void ld4(ull* d, const float* p) {
    ulonglong2 t0 = *(const ulonglong2*)(p);
    ulonglong2 t1 = *(const ulonglong2*)(p + 4);
    d[0] = t0.x; d[1] = t0.y; d[2] = t1.x; d[3] = t1.y;
}

__device__ __forceinline__ void dot3v(const ull* q, const ull* k, const ull* qa,
                                      const ull* X0, const ull* X1,
                                      float4* d0, float4* d1)
{
    ull A0 = mul2(q[0], X0[0]),  A1 = mul2(q[0], X1[0]);
    ull C0 = mul2(k[0], X0[0]),  C1 = mul2(k[0], X1[0]);
    ull Y0 = mul2(qa[0], X0[0]), Y1 = mul2(qa[0], X1[0]);
    #pragma unroll
    for (int t = 1; t < 4; t++) {
        A0 = fma2(q[t], X0[t], A0);  A1 = fma2(q[t], X1[t], A1);
        C0 = fma2(k[t], X0[t], C0);  C1 = fma2(k[t], X1[t], C1);
        Y0 = fma2(qa[t], X0[t], Y0); Y1 = fma2(qa[t], X1[t], Y1);
    }
    float2 a0 = unpack2(A0), c0 = unpack2(C0), y0 = unpack2(Y0);
    float2 a1 = unpack2(A1), c1 = unpack2(C1), y1 = unpack2(Y1);
    *d0 = make_float4(a0.x + a0.y, c0.x + c0.y, y0.x + y0.y, 0.f);
    *d1 = make_float4(a1.x + a1.y, c1.x + c1.y, y1.x + y1.y, 0.f);
}

__device__ __forceinline__ float4 sum8(const float4* p)
{
    float4 x0 = p[0], x1 = p[1], x2 = p[2], x3 = p[3];
    float4 x4 = p[4], x5 = p[5], x6 = p[6], x7 = p[7];
    float4 r;
    r.x = ((x0.x + x1.x) + (x2.x + x3.x)) + ((x4.x + x5.x) + (x6.x + x7.x));
    r.y = ((x0.y + x1.y) + (x2.y + x3.y)) + ((x4.y + x5.y) + (x6.y + x7.y));
    r.z = ((x0.z + x1.z) + (x2.z + x3.z)) + ((x4.z + x5.z) + (x6.z + x7.z));
    r.w = 0.f;
    return r;
}

__global__ void __launch_bounds__(288, 1) scan_kernel()
{
    __shared__ __align__(16) float  stg[8][REC_];        // 10752 B
    __shared__ __align__(16) float4 part[2][2][576];     // 36864 B
    __shared__ __align__(16) float  swb[2][128];         // 1024 B

    const int b   = blockIdx.x;
    const int tid = threadIdx.x;
    const float* base = g_inp + (size_t)b * S_ * REC_;
    float* yb = g_y + (size_t)b * S_ * DS_;

    if (tid < 128) swb[0][tid] = 0.0f;
    for (int x = tid; x < 1152; x += 288) ((float4*)part)[x] = make_float4(0.f, 0.f, 0.f, 0.f);

    const int pr   = (tid >= 84 && tid < 168) ? 1 : 0;
    const int poff = (tid - pr * 84) * 4;
    #pragma unroll
    for (int gp = 0; gp < 3; gp++) {            // recs 0..5, 2 per group
        int rec = 2 * gp + pr;
        if (tid < 168) cp_async16(&stg[rec & 7][poff], base + (size_t)rec * REC_ + poff);
        CP_COMMIT();
    }
    CP_WAIT1();                                 // recs 0..3 ready
    __syncthreads();

    if (tid < 256) {
        // ================= vector warps =================
        const int kg = tid & 7;
        const int vp = tid >> 3;
        const int v0 = vp * 2;
        const int ko = kg * 8;
        const int pi0 = v0 * 9 + kg;

        ull U0[4], U1[4], kmA[4], kmB[4], aB[4], aC[4];
        #pragma unroll
        for (int t = 0; t < 4; t++) {
            U0[t] = 0ull; U1[t] = 0ull;
            kmA[t] = 0ull; kmB[t] = 0ull; aB[t] = 0ull; aC[t] = 0ull;
        }

        for (int j = 0; j < S_ / 2; j++) {
            const int i = 2 * j;
            const float* r0 = stg[i & 7];
            const float* r1 = stg[(i + 1) & 7];
            const float* r2 = stg[(i + 2) & 7];
            const float* r3 = stg[(i + 3) & 7];

            {   // prefetch recs i+6, i+7 (slots (i-2)&7, (i-1)&7: dead)
                int rec = i + 6 + pr;
                if (tid < 168 && rec < S_)
                    cp_async16(&stg[rec & 7][poff], base + (size_t)rec * REC_ + poff);
            }
            CP_COMMIT();

            float4 sw4 = *(const float4*)&swb[j & 1][v0 * 2]; // (E,O) x 2v
            ull swE0 = pack2(sw4.x, sw4.x), swO0 = pack2(sw4.y, sw4.y);
            ull swE1 = pack2(sw4.z, sw4.z), swO1 = pack2(sw4.w, sw4.w);

            // H_{i-2} = U + swE*kmA ; H_{i-1} = aB*H + swO*kmB ; U = aC*H_{i-1}
            #pragma unroll
            for (int t = 0; t < 4; t++) {
                ull h0 = fma2(kmA[t], swE0, U0[t]);
                ull h1 = fma2(kmA[t], swE1, U1[t]);
                h0 = fma2(kmB[t], swO0, mul2(aB[t], h0));
                h1 = fma2(kmB[t], swO1, mul2(aB[t], h1));
                U0[t] = mul2(aC[t], h0);
                U1[t] = mul2(aC[t], h1);
            }

            // new carries for next epoch
            ld4(kmA, r0 + 192 + ko);    // km_i
            ld4(kmB, r1 + 192 + ko);    // km_{i+1}
            ull aD[4], aE[4];
            ld4(aD, r1 + 128 + ko);     // a_{i+1}
            ld4(aE, r2 + 128 + ko);     // a_{i+2}

            ull B10[4], B11[4];
            #pragma unroll
            for (int t = 0; t < 4; t++) { B10[t] = mul2(aD[t], U0[t]); B11[t] = mul2(aD[t], U1[t]); }

            ull q2[4], k2[4], qa2[4];
            ld4(q2, r2 + ko);
            ld4(k2, r2 + 64 + ko);
            #pragma unroll
            for (int t = 0; t < 4; t++) qa2[t] = mul2(q2[t], aE[t]);

            float4* pd = &part[(j + 1) & 1][0][0];
            dot3v(q2, k2, qa2, B10, B11, &pd[pi0], &pd[pi0 + 9]);

            #pragma unroll
            for (int t = 0; t < 4; t++) { B10[t] = mul2(aE[t], B10[t]); B11[t] = mul2(aE[t], B11[t]); }
            ull q3[4], k3[4], a3[4], qa3[4];
            ld4(q3, r3 + ko);
            ld4(k3, r3 + 64 + ko);
            ld4(a3, r3 + 128 + ko);
            #pragma unroll
            for (int t = 0; t < 4; t++) qa3[t] = mul2(q3[t], a3[t]);

            pd = &part[(j + 1) & 1][1][0];
            dot3v(q3, k3, qa3, B10, B11, &pd[pi0], &pd[pi0 + 9]);

            #pragma unroll
            for (int t = 0; t < 4; t++) { aB[t] = aD[t]; aC[t] = aE[t]; }

            CP_WAIT1();
            BAR0();
        }
    } else {
        // ================= sequencer warp =================
        const int lane = tid - 256;
        float p20 = 0.f, p21 = 0.f, p10 = 0.f, p11 = 0.f;  // lag-2, lag-1 s*w per v

        for (int j = 0; j < S_ / 2; j++) {
            const int i = 2 * j;
            const float* re = stg[i & 7];
            const float* ro = stg[(i + 1) & 7];
            const float4* pe = &part[j & 1][0][0];
            const float4* po = &part[j & 1][1][0];

            float4 E0 = sum8(pe + lane * 9);
            float4 E1 = sum8(pe + (lane + 32) * 9);
            float4 O0 = sum8(po + lane * 9);
            float4 O1 = sum8(po + (lane + 32) * 9);

            float vE0 = re[256 + lane], vE1 = re[288 + lane];
            float vO0 = ro[256 + lane], vO1 = ro[288 + lane];
            float4 s1e = *(const float4*)&re[320];  // g1A g1C c g1Y
            float4 s2e = *(const float4*)&re[324];  // g2A g2C g2Y g3A
            float4 s1o = *(const float4*)&ro[320];
            float4 s2o = *(const float4*)&ro[324];
            float2 s3o = *(const float2*)&ro[328];  // g3C g3Y

            // ---- even step i ----
            float u0 = vE0 - E0.x - p20 * s2e.x - p10 * s1e.x;
            float u1 = vE1 - E1.x - p21 * s2e.x - p11 * s1e.x;
            float e = u0 * u0 + u1 * u1;
            e += __shfl_xor_sync(~0u, e, 1);  e += __shfl_xor_sync(~0u, e, 2);
            e += __shfl_xor_sync(~0u, e, 4);  e += __shfl_xor_sync(~0u, e, 8);
            e += __shfl_xor_sync(~0u, e, 16);
            float sE;
            asm("tanh.approx.f32 %0, %1;" : "=f"(sE) : "f"(e * 0.499999495f));
            sE = fmaf(0.5f, sE, 0.5f);
            float wE0 = vE0 - (E0.y + p20 * s2e.y + p10 * s1e.y);
            float wE1 = vE1 - (E1.y + p21 * s2e.y + p11 * s1e.y);
            float pE0 = sE * wE0, pE1 = sE * wE1;
            yb[(size_t)i * DS_ + lane]      = E0.z + p20 * s2e.z + p10 * s1e.w + s1e.z * pE0;
            yb[(size_t)i * DS_ + lane + 32] = E1.z + p21 * s2e.z + p11 * s1e.w + s1e.z * pE1;

            // ---- odd step i+1 ----
            u0 = vO0 - O0.x - p20 * s2o.w - p10 * s2o.x - pE0 * s1o.x;
            u1 = vO1 - O1.x - p21 * s2o.w - p11 * s2o.x - pE1 * s1o.x;
            e = u0 * u0 + u1 * u1;
            e += __shfl_xor_sync(~0u, e, 1);  e += __shfl_xor_sync(~0u, e, 2);
            e += __shfl_xor_sync(~0u, e, 4);  e += __shfl_xor_sync(~0u, e, 8);
            e += __shfl_xor_sync(~0u, e, 16);
            float sO;
            asm("tanh.approx.f32 %0, %1;" : "=f"(sO) : "f"(e * 0.499999495f));
            sO = fmaf(0.5f, sO, 0.5f);
            float wO0 = vO0 - (O0.y + p20 * s3o.x + p10 * s2o.y + pE0 * s1o.y);
            float wO1 = vO1 - (O1.y + p21 * s3o.x + p11 * s2o.y + pE1 * s1o.y);
            float pO0 = sO * wO0, pO1 = sO * wO1;
            yb[(size_t)(i + 1) * DS_ + lane]      = O0.z + p20 * s3o.y + p10 * s2o.z + pE0 * s1o.w + s1o.z * pO0;
            yb[(size_t)(i + 1) * DS_ + lane + 32] = O1.z + p21 * s3o.y + p11 * s2o.z + pE1 * s1o.w + s1o.z * pO1;

            float* sd = swb[(j + 1) & 1];
            *(float2*)&sd[lane * 2]        = make_float2(pE0, pO0);
            *(float2*)&sd[(lane + 32) * 2] = make_float2(pE1, pO1);
            p20 = pE0; p21 = pE1; p10 = pO0; p11 = pO1;

            BAR0();
        }
    }
}

// =====================================================================
// Kernel D: RMS-norm(y)*norm_w @ Wo^T -> out (proven)
// =====================================================================
__global__ void __launch_bounds__(256) out_gemm(
    const float* __restrict__ norm_w, const float* __restrict__ Wo,
    float* __restrict__ out)
{
    __shared__ __align__(16) float ys[32 * 64];
    __shared__ __align__(16) float wos[64 * 128];
    __shared__ float rs[32];
    __shared__ float nws[64];

    const int tid = threadIdx.x;
    const int m0 = blockIdx.y * 32;
    const int n0 = blockIdx.x * 128;

    for (int i = tid * 4; i < 2048; i += 1024)
        *(float4*)&ys[i] = *(const float4*)&g_y[(size_t)m0 * 64 + i];
    if (tid < 64) nws[tid] = norm_w[tid];
    {
        int n  = tid & 127;
        int vb = tid >> 7;
        #pragma unroll
        for (int q = 0; q < 8; q++) {
            int v4 = vb * 8 + q;
            float4 w = *(const float4*)&Wo[(size_t)(n0 + n) * 64 + v4 * 4];
            wos[(v4 * 4 + 0) * 128 + n] = w.x;
            wos[(v4 * 4 + 1) * 128 + n] = w.y;
            wos[(v4 * 4 + 2) * 128 + n] = w.z;
            wos[(v4 * 4 + 3) * 128 + n] = w.w;
        }
    }
    __syncthreads();

    {
        int r = tid >> 3, p = tid & 7;
        float sum = 0.0f;
        #pragma unroll
        for (int j = 0; j < 8; j++) { float x = ys[r * 64 + p * 8 + j]; sum += x * x; }
        sum += __shfl_xor_sync(~0u, sum, 1);
        sum += __shfl_xor_sync(~0u, sum, 2);
        sum += __shfl_xor_sync(~0u, sum, 4);
        if (p == 0) rs[r] = rsqrtf(sum * (1.0f / 64.0f) + 1e-6f);
    }
    __syncthreads();
    for (int i = tid; i < 2048; i += 256)
        ys[i] = ys[i] * rs[i >> 6] * nws[i & 63];
    __syncthreads();

    const int tn = tid & 31;
    const int tm = tid >> 5;
    float acc[4][4];
    #pragma unroll
    for (int i = 0; i < 4; i++)
        #pragma unroll
        for (int j = 0; j < 4; j++) acc[i][j] = 0.0f;

    #pragma unroll 8
    for (int vv = 0; vv < 64; vv++) {
        float b0 = wos[vv * 128 + tn];
        float b1 = wos[vv * 128 + tn + 32];
        float b2 = wos[vv * 128 + tn + 64];
        float b3 = wos[vv * 128 + tn + 96];
        #pragma unroll
        for (int i = 0; i < 4; i++) {
            float a = ys[(tm * 4 + i) * 64 + vv];
            acc[i][0] += a * b0; acc[i][1] += a * b1;
            acc[i][2] += a * b2; acc[i][3] += a * b3;
        }
    }
    #pragma unroll
    for (int i = 0; i < 4; i++) {
        size_t row = (size_t)(m0 + tm * 4 + i) * 2048 + n0 + tn;
        #pragma unroll
        for (int j = 0; j < 4; j++) out[row + 32 * j] = acc[i][j];
    }
}

// =====================================================================
extern "C" void kernel_launch(void* const* d_in, const int* in_sizes, int n_in,
                              void* d_out, int out_size)
{
    const float* x      = (const float*)d_in[0];
    const float* Wk     = (const float*)d_in[1];
    const float* Wv     = (const float*)d_in[2];
    const float* Wq     = (const float*)d_in[3];
    const float* Wa_w   = (const float*)d_in[4];
    const float* Wa_b   = (const float*)d_in[5];
    const float* lam    = (const float*)d_in[6];
    const float* norm_w = (const float*)d_in[7];
    const float* Wo     = (const float*)d_in[8];
    float* out = (float*)d_out;

    proj_gemm<<<dim3(128, 4), 256>>>(x, Wk, Wv, Wq, Wa_w);
    prep_kernel<<<1024, 256>>>(Wa_b, lam);
    ghc_kernel<<<1024, 256>>>();
    scan_kernel<<<4, 288>>>();
    out_gemm<<<dim3(16, 256), 256>>>(norm_w, Wo, out);
}

// round 16
// speedup vs baseline: 1.0445x; 1.0445x over previous
#include <cuda_runtime.h>
#include <cstdint>

typedef unsigned long long ull;

#define B_   4
#define S_   2048
#define DM_  2048
#define DS_  64
#define REC_ 336
// record: q[0:64] k[64:128] a[128:192] km[192:256] v[256:320]
// scalars: [320]g1A [321]g1C [322]c [323]g1Y [324]g2A [325]g2C [326]g2Y
//          [327]g3A [328]g3C [329]g3Y

__device__ __forceinline__ ull fma2(ull a, ull b, ull c) {
    ull d; asm("fma.rn.f32x2 %0,%1,%2,%3;" : "=l"(d) : "l"(a), "l"(b), "l"(c)); return d;
}
__device__ __forceinline__ ull mul2(ull a, ull b) {
    ull d; asm("mul.rn.f32x2 %0,%1,%2;" : "=l"(d) : "l"(a), "l"(b)); return d;
}
__device__ __forceinline__ ull pack2(float lo, float hi) {
    ull d; asm("mov.b64 %0, {%1,%2};" : "=l"(d) : "f"(lo), "f"(hi)); return d;
}
__device__ __forceinline__ float2 unpack2(ull a) {
    float lo, hi; asm("mov.b64 {%0,%1}, %2;" : "=f"(lo), "=f"(hi) : "l"(a));
    return make_float2(lo, hi);
}
__device__ __forceinline__ void cp_async16(void* smem, const void* gmem) {
    uint32_t s = (uint32_t)__cvta_generic_to_shared(smem);
    asm volatile("cp.async.cg.shared.global [%0], [%1], 16;" :: "r"(s), "l"(gmem) : "memory");
}
#define CP_COMMIT()  asm volatile("cp.async.commit_group;" ::: "memory")
#define CP_WAIT1()   asm volatile("cp.async.wait_group 1;" ::: "memory")
#define BAR0()       asm volatile("bar.sync 0;" ::: "memory")

__device__ float g_raw[B_ * S_ * 256];
__device__ float g_inp[B_ * S_ * REC_];
__device__ float g_y  [B_ * S_ * DS_];

// =====================================================================
// Kernel A: projection GEMM (proven)
// =====================================================================
#define BM 64
#define BN 64
#define BK 32

__global__ void __launch_bounds__(256) proj_gemm(
    const float* __restrict__ x,
    const float* __restrict__ Wk, const float* __restrict__ Wv,
    const float* __restrict__ Wq, const float* __restrict__ Wa)
{
    __shared__ __align__(16) float As[BK][BM + 4];
    __shared__ __align__(16) float Bs[BK][BN + 4];

    const int mt = blockIdx.x;
    const int nt = blockIdx.y;
    const float* W = (nt == 0) ? Wk : (nt == 1) ? Wv : (nt == 2) ? Wq : Wa;

    const int tid  = threadIdx.x;
    const int lrow = tid >> 2;
    const int lk   = (tid & 3) * 4;
    const float* xg = x + (size_t)(mt * BM + lrow) * DM_ + lk;
    const float* wg = W + (size_t)lrow * DM_ + lk;

    const int tn4 = (tid & 15) * 4;
    const int tm4 = (tid >> 4) * 4;

    ull acc[4][2];
    #pragma unroll
    for (int i = 0; i < 4; i++) { acc[i][0] = 0ull; acc[i][1] = 0ull; }

    float4 av0 = *(const float4*)xg;
    float4 av1 = *(const float4*)(xg + 16);
    float4 bv0 = *(const float4*)wg;
    float4 bv1 = *(const float4*)(wg + 16);

    for (int k0 = 0; k0 < DM_; k0 += BK) {
        __syncthreads();
        As[lk + 0][lrow] = av0.x; As[lk + 1][lrow] = av0.y;
        As[lk + 2][lrow] = av0.z; As[lk + 3][lrow] = av0.w;
        As[lk + 16][lrow] = av1.x; As[lk + 17][lrow] = av1.y;
        As[lk + 18][lrow] = av1.z; As[lk + 19][lrow] = av1.w;
        Bs[lk + 0][lrow] = bv0.x; Bs[lk + 1][lrow] = bv0.y;
        Bs[lk + 2][lrow] = bv0.z; Bs[lk + 3][lrow] = bv0.w;
        Bs[lk + 16][lrow] = bv1.x; Bs[lk + 17][lrow] = bv1.y;
        Bs[lk + 18][lrow] = bv1.z; Bs[lk + 19][lrow] = bv1.w;
        if (k0 + BK < DM_) {
            av0 = *(const float4*)(xg + k0 + BK);
            av1 = *(const float4*)(xg + k0 + BK + 16);
            bv0 = *(const float4*)(wg + k0 + BK);
            bv1 = *(const float4*)(wg + k0 + BK + 16);
        }
        __syncthreads();
        #pragma unroll
        for (int kk = 0; kk < BK; kk++) {
            ulonglong2 bb = *(const ulonglong2*)&Bs[kk][tn4];
            float4 a4 = *(const float4*)&As[kk][tm4];
            ull p0 = pack2(a4.x, a4.x), p1 = pack2(a4.y, a4.y);
            ull p2 = pack2(a4.z, a4.z), p3 = pack2(a4.w, a4.w);
            acc[0][0] = fma2(p0, bb.x, acc[0][0]); acc[0][1] = fma2(p0, bb.y, acc[0][1]);
            acc[1][0] = fma2(p1, bb.x, acc[1][0]); acc[1][1] = fma2(p1, bb.y, acc[1][1]);
            acc[2][0] = fma2(p2, bb.x, acc[2][0]); acc[2][1] = fma2(p2, bb.y, acc[2][1]);
            acc[3][0] = fma2(p3, bb.x, acc[3][0]); acc[3][1] = fma2(p3, bb.y, acc[3][1]);
        }
    }

    #pragma unroll
    for (int i = 0; i < 4; i++) {
        int m = mt * BM + tm4 + i;
        #pragma unroll
        for (int j = 0; j < 2; j++) {
            float2 f = unpack2(acc[i][j]);
            *(float2*)&g_raw[(size_t)m * 256 + nt * 64 + tn4 + 2 * j] = f;
        }
    }
}

// =====================================================================
// Kernel B: per-token prep (proven)
// =====================================================================
__global__ void __launch_bounds__(256) prep_kernel(
    const float* __restrict__ Wa_b, const float* __restrict__ lam)
{
    const int g    = blockIdx.x * 8 + (threadIdx.x >> 5);
    const int lane = threadIdx.x & 31;
    const float* r_ = g_raw + (size_t)g * 256;

    float k0 = r_[lane],        k1 = r_[lane + 32];
    float v0 = r_[64 + lane],   v1 = r_[96 + lane];
    float q0 = r_[128 + lane],  q1 = r_[160 + lane];
    float z0 = r_[192 + lane] + Wa_b[lane];
    float z1 = r_[224 + lane] + Wa_b[lane + 32];

    float kn = k0 * k0 + k1 * k1;
    #pragma unroll
    for (int m = 1; m < 32; m <<= 1) kn += __shfl_xor_sync(~0u, kn, m);
    float kinv = 1.0f / fmaxf(sqrtf(kn), 1e-12f);
    k0 *= kinv; k1 *= kinv;

    float qn = q0 * q0 + q1 * q1;
    #pragma unroll
    for (int m = 1; m < 32; m <<= 1) qn += __shfl_xor_sync(~0u, qn, m);
    float qinv = 1.0f / fmaxf(sqrtf(qn), 1e-12f);
    q0 *= qinv; q1 *= qinv;

    float la0 = logf(1.0f / (1.0f + expf(-lam[lane])) + 1e-8f);
    float la1 = logf(1.0f / (1.0f + expf(-lam[lane + 32])) + 1e-8f);
    float rr0 = 1.0f / (1.0f + expf(-z0));
    float rr1 = 1.0f / (1.0f + expf(-z1));
    float al0 = expf(8.0f * rr0 * la0);
    float al1 = expf(8.0f * rr1 * la1);
    float km0 = k0 * (1.0f - al0), km1 = k1 * (1.0f - al1);

    float c = q0 * km0 + q1 * km1;
    #pragma unroll
    for (int m = 1; m < 32; m <<= 1) c += __shfl_xor_sync(~0u, c, m);

    float* o = g_inp + (size_t)g * REC_;
    o[lane] = q0;          o[lane + 32] = q1;
    o[64 + lane] = k0;     o[96 + lane] = k1;
    o[128 + lane] = al0;   o[160 + lane] = al1;
    o[192 + lane] = km0;   o[224 + lane] = km1;
    o[256 + lane] = v0;    o[288 + lane] = v1;
    if (lane == 0) o[322] = c;
}

// =====================================================================
// Kernel B2: lag-1/2/3 scalars (proven in R14)
// =====================================================================
__global__ void __launch_bounds__(256) ghc_kernel()
{
    const int g    = blockIdx.x * 8 + (threadIdx.x >> 5);
    const int lane = threadIdx.x & 31;
    const int t    = g & (S_ - 1);
    float* cur = g_inp + (size_t)g * REC_;
    const float* p1 = cur - REC_;
    const float* p2 = cur - 2 * REC_;
    const float* p3 = cur - 3 * REC_;

    float m10 = 0.f, m11 = 0.f, m20 = 0.f, m21 = 0.f, m30 = 0.f, m31 = 0.f;
    if (t >= 1) { m10 = p1[192 + lane]; m11 = p1[224 + lane]; }
    if (t >= 2) {
        float a10 = p1[128 + lane], a11 = p1[160 + lane];
        m20 = a10 * p2[192 + lane]; m21 = a11 * p2[224 + lane];
        if (t >= 3) {
            m30 = a10 * p2[128 + lane] * p3[192 + lane];
            m31 = a11 * p2[160 + lane] * p3[224 + lane];
        }
    }
    float q0 = cur[lane], q1 = cur[lane + 32];
    float k0 = cur[64 + lane], k1 = cur[96 + lane];
    float a0 = cur[128 + lane], a1 = cur[160 + lane];
    float y0 = q0 * a0, y1 = q1 * a1;

    float vv[9];
    vv[0] = q0*m10 + q1*m11; vv[1] = k0*m10 + k1*m11; vv[2] = y0*m10 + y1*m11;
    vv[3] = q0*m20 + q1*m21; vv[4] = k0*m20 + k1*m21; vv[5] = y0*m20 + y1*m21;
    vv[6] = q0*m30 + q1*m31; vv[7] = k0*m30 + k1*m31; vv[8] = y0*m30 + y1*m31;
    #pragma unroll
    for (int x = 0; x < 9; x++)
        #pragma unroll
        for (int m = 1; m < 32; m <<= 1) vv[x] += __shfl_xor_sync(~0u, vv[x], m);

    if (lane == 0) {
        cur[320] = vv[0]; cur[321] = vv[1]; cur[323] = vv[2];
        cur[324] = vv[3]; cur[325] = vv[4]; cur[326] = vv[5];
        cur[327] = vv[6]; cur[328] = vv[7]; cur[329] = vv[8];
    }
}

// =====================================================================
// Kernel C: 2-token-epoch scan (R14 structure) with SINGLE parallel
// reduction per epoch: even e + odd P/Q/R reduced together.
// =====================================================================
__device__ __forceinline__ void ld4(ull* d, const float* p) {
    ulonglong2 t0 = *(const ulonglong2*)(p);
    ulonglong2 t1 = *(const ulonglong2*)(p + 4);
    d[0] = t0.x; d[1] = t0.y; d[2] = t1.x; d[3] = t1.y;
}

__device__ __forceinline__ void dot3v(const ull* q, const ull* k, const ull* qa,
                                      const ull* X0, const ull* X1,
                                      float4* d0, float4* d1)
{
    ull A0 = mul2(q[0], X0[0]),  A1 = mul2(q[0], X1[0]);
    ull C0 = mul2(k[0], X0[0]),  C1 = mul2(k[0], X1[0]);
    ull Y0 = mul2(qa[0], X0[0]), Y1 = mul2(qa[0], X1[0]);
    #pragma unroll
    for (int t = 1; t < 4; t++) {
        A0 = fma2(q[t], X0[t], A0);  A1 = fma2(q[t], X1[t], A1);
        C0 = fma2(k[t], X0[t], C0);  C1 = fma2(k[t], X1[t], C1);
        Y0 = fma2(qa[t], X0[t], Y0); Y1 = fma2(qa[t], X1[t], Y1);
    }
    float2 a0 = unpack2(A0), c0 = unpack2(C0), y0 = unpack2(Y0);
    float2 a1 = unpack2(A1), c1 = unpack2(C1), y1 = unpack2(Y1);
    *d0 = make_float4(a0.x + a0.y, c0.x + c0.y, y0.x + y0.y, 0.f);
    *d1 = make_float4(a1.x + a1.y, c1.x + c1.y, y1.x + y1.y, 0.f);
}

__device__ __forceinline__ float4 sum8(const float4* p)
{
    float4 x0 = p[0], x1 = p[1], x2 = p[2], x3 = p[3];
    float4 x4 = p[4], x5 = p[5], x6 = p[6], x7 = p[7];
    float4 r;
    r.x = ((x0.x + x1.x) + (x2.x + x3.x)) + ((x4.x + x5.x) + (x6.x + x7.x));
    r.y = ((x0.y + x1.y) + (x2.y + x3.y)) + ((x4.y + x5.y) + (x6.y + x7.y));
    r.z = ((x0.z + x1.z) + (x2.z + x3.z)) + ((x4.z + x5.z) + (x6.z + x7.z));
    r.w = 0.f;
    return r;
}

__global__ void __launch_bounds__(288, 1) scan_kernel()
{
    __shared__ __align__(16) float  stg[8][REC_];        // 10752 B
    __shared__ __align__(16) float4 part[2][2][576];     // 36864 B
    __shared__ __align__(16) float  swb[2][128];         // 1024 B

    const int b   = blockIdx.x;
    const int tid = threadIdx.x;
    const float* base = g_inp + (size_t)b * S_ * REC_;
    float* yb = g_y + (size_t)b * S_ * DS_;

    if (tid < 128) swb[0][tid] = 0.0f;
    for (int x = tid; x < 1152; x += 288) ((float4*)part)[x] = make_float4(0.f, 0.f, 0.f, 0.f);

    const int pr   = (tid >= 84 && tid < 168) ? 1 : 0;
    const int poff = (tid - pr * 84) * 4;
    #pragma unroll
    for (int gp = 0; gp < 3; gp++) {
        int rec = 2 * gp + pr;
        if (tid < 168) cp_async16(&stg[rec & 7][poff], base + (size_t)rec * REC_ + poff);
        CP_COMMIT();
    }
    CP_WAIT1();
    __syncthreads();

    if (tid < 256) {
        // ================= vector warps (identical to R14) =================
        const int kg = tid & 7;
        const int vp = tid >> 3;
        const int v0 = vp * 2;
        const int ko = kg * 8;
        const int pi0 = v0 * 9 + kg;

        ull U0[4], U1[4], kmA[4], kmB[4], aB[4], aC[4];
        #pragma unroll
        for (int t = 0; t < 4; t++) {
            U0[t] = 0ull; U1[t] = 0ull;
            kmA[t] = 0ull; kmB[t] = 0ull; aB[t] = 0ull; aC[t] = 0ull;
        }

        for (int j = 0; j < S_ / 2; j++) {
            const int i = 2 * j;
            const float* r0 = stg[i & 7];
            const float* r1 = stg[(i + 1) & 7];
            const float* r2 = stg[(i + 2) & 7];
            const float* r3 = stg[(i + 3) & 7];

            {
                int rec = i + 6 + pr;
                if (tid < 168 && rec < S_)
                    cp_async16(&stg[rec & 7][poff], base + (size_t)rec * REC_ + poff);
            }
            CP_COMMIT();

            float4 sw4 = *(const float4*)&swb[j & 1][v0 * 2];
            ull swE0 = pack2(sw4.x, sw4.x), swO0 = pack2(sw4.y, sw4.y);
            ull swE1 = pack2(sw4.z, sw4.z), swO1 = pack2(sw4.w, sw4.w);

            #pragma unroll
            for (int t = 0; t < 4; t++) {
                ull h0 = fma2(kmA[t], swE0, U0[t]);
                ull h1 = fma2(kmA[t], swE1, U1[t]);
                h0 = fma2(kmB[t], swO0, mul2(aB[t], h0));
                h1 = fma2(kmB[t], swO1, mul2(aB[t], h1));
                U0[t] = mul2(aC[t], h0);
                U1[t] = mul2(aC[t], h1);
            }

            ld4(kmA, r0 + 192 + ko);
            ld4(kmB, r1 + 192 + ko);
            ull aD[4], aE[4];
            ld4(aD, r1 + 128 + ko);
            ld4(aE, r2 + 128 + ko);

            ull B10[4], B11[4];
            #pragma unroll
            for (int t = 0; t < 4; t++) { B10[t] = mul2(aD[t], U0[t]); B11[t] = mul2(aD[t], U1[t]); }

            ull q2[4], k2[4], qa2[4];
            ld4(q2, r2 + ko);
            ld4(k2, r2 + 64 + ko);
            #pragma unroll
            for (int t = 0; t < 4; t++) qa2[t] = mul2(q2[t], aE[t]);

            float4* pd = &part[(j + 1) & 1][0][0];
            dot3v(q2, k2, qa2, B10, B11, &pd[pi0], &pd[pi0 + 9]);

            #pragma unroll
            for (int t = 0; t < 4; t++) { B10[t] = mul2(aE[t], B10[t]); B11[t] = mul2(aE[t], B11[t]); }
            ull q3[4], k3[4], a3[4], qa3[4];
            ld4(q3, r3 + ko);
            ld4(k3, r3 + 64 + ko);
            ld4(a3, r3 + 128 + ko);
            #pragma unroll
            for (int t = 0; t < 4; t++) qa3[t] = mul2(q3[t], a3[t]);

            pd = &part[(j + 1) & 1][1][0];
            dot3v(q3, k3, qa3, B10, B11, &pd[pi0], &pd[pi0 + 9]);

            #pragma unroll
            for (int t = 0; t < 4; t++) { aB[t] = aD[t]; aC[t] = aE[t]; }

            CP_WAIT1();
            BAR0();
        }
    } else {
        // ================= sequencer: one parallel 4-value reduction =================
        const int lane = tid - 256;
        float p20 = 0.f, p21 = 0.f, p10 = 0.f, p11 = 0.f;

        for (int j = 0; j < S_ / 2; j++) {
            const int i = 2 * j;
            const float* re = stg[i & 7];
            const float* ro = stg[(i + 1) & 7];
            const float4* pe = &part[j & 1][0][0];
            const float4* po = &part[j & 1][1][0];

            float4 E0 = sum8(pe + lane * 9);
            float4 E1 = sum8(pe + (lane + 32) * 9);
            float4 O0 = sum8(po + lane * 9);
            float4 O1 = sum8(po + (lane + 32) * 9);

            float vE0 = re[256 + lane], vE1 = re[288 + lane];
            float vO0 = ro[256 + lane], vO1 = ro[288 + lane];
            float4 s1e = *(const float4*)&re[320];  // g1A g1C c g1Y
            float4 s2e = *(const float4*)&re[324];  // g2A g2C g2Y g3A
            float4 s1o = *(const float4*)&ro[320];
            float4 s2o = *(const float4*)&ro[324];
            float2 s3o = *(const float2*)&ro[328];  // g3C g3Y

            // sE-independent per-v quantities
            float uE0 = vE0 - E0.x - p20 * s2e.x - p10 * s1e.x;
            float uE1 = vE1 - E1.x - p21 * s2e.x - p11 * s1e.x;
            float wE0 = vE0 - (E0.y + p20 * s2e.y + p10 * s1e.y);
            float wE1 = vE1 - (E1.y + p21 * s2e.y + p11 * s1e.y);
            float bO0 = vO0 - O0.x - p20 * s2o.w - p10 * s2o.x;
            float bO1 = vO1 - O1.x - p21 * s2o.w - p11 * s2o.x;

            // 4-value parallel butterfly: e, P, Q, R
            float e = uE0 * uE0 + uE1 * uE1;
            float P = bO0 * bO0 + bO1 * bO1;
            float Q = bO0 * wE0 + bO1 * wE1;
            float R = wE0 * wE0 + wE1 * wE1;
            #pragma unroll
            for (int m = 1; m < 32; m <<= 1) {
                e += __shfl_xor_sync(~0u, e, m);
                P += __shfl_xor_sync(~0u, P, m);
                Q += __shfl_xor_sync(~0u, Q, m);
                R += __shfl_xor_sync(~0u, R, m);
            }

            float sE;
            asm("tanh.approx.f32 %0, %1;" : "=f"(sE) : "f"(e * 0.499999495f));
            sE = fmaf(0.5f, sE, 0.5f);

            float sg = sE * s1o.x;
            float eO = P + sg * (sg * R - 2.0f * Q);
            float sO;
            asm("tanh.approx.f32 %0, %1;" : "=f"(sO) : "f"(eO * 0.499999495f));
            sO = fmaf(0.5f, sO, 0.5f);

            float pE0 = sE * wE0, pE1 = sE * wE1;
            float wO0 = vO0 - (O0.y + p20 * s3o.x + p10 * s2o.y + pE0 * s1o.y);
            float wO1 = vO1 - (O1.y + p21 * s3o.x + p11 * s2o.y + pE1 * s1o.y);
            float pO0 = sO * wO0, pO1 = sO * wO1;

            float* sd = swb[(j + 1) & 1];
            *(float2*)&sd[lane * 2]        = make_float2(pE0, pO0);
            *(float2*)&sd[(lane + 32) * 2] = make_float2(pE1, pO1);

            yb[(size_t)i * DS_ + lane]      = E0.z + p20 * s2e.z + p10 * s1e.w + s1e.z * pE0;
            yb[(size_t)i * DS_ + lane + 32] = E1.z + p21 * s2e.z + p11 * s1e.w + s1e.z * pE1;
            yb[(size_t)(i + 1) * DS_ + lane]      = O0.z + p20 * s3o.y + p10 * s2o.z + pE0 * s1o.w + s1o.z * pO0;
            yb[(size_t)(i + 1) * DS_ + lane + 32] = O1.z + p21 * s3o.y + p11 * s2o.z + pE1 * s1o.w + s1o.z * pO1;

            p20 = pE0; p21 = pE1; p10 = pO0; p11 = pO1;
            BAR0();
        }
    }
}

// =====================================================================
// Kernel D: RMS-norm(y)*norm_w @ Wo^T -> out (proven)
// =====================================================================
__global__ void __launch_bounds__(256) out_gemm(
    const float* __restrict__ norm_w, const float* __restrict__ Wo,
    float* __restrict__ out)
{
    __shared__ __align__(16) float ys[32 * 64];
    __shared__ __align__(16) float wos[64 * 128];
    __shared__ float rs[32];
    __shared__ float nws[64];

    const int tid = threadIdx.x;
    const int m0 = blockIdx.y * 32;
    const int n0 = blockIdx.x * 128;

    for (int i = tid * 4; i < 2048; i += 1024)
        *(float4*)&ys[i] = *(const float4*)&g_y[(size_t)m0 * 64 + i];
    if (tid < 64) nws[tid] = norm_w[tid];
    {
        int n  = tid & 127;
        int vb = tid >> 7;
        #pragma unroll
        for (int q = 0; q < 8; q++) {
            int v4 = vb * 8 + q;
            float4 w = *(const float4*)&Wo[(size_t)(n0 + n) * 64 + v4 * 4];
            wos[(v4 * 4 + 0) * 128 + n] = w.x;
            wos[(v4 * 4 + 1) * 128 + n] = w.y;
            wos[(v4 * 4 + 2) * 128 + n] = w.z;
            wos[(v4 * 4 + 3) * 128 + n] = w.w;
        }
    }
    __syncthreads();

    {
        int r = tid >> 3, p = tid & 7;
        float sum = 0.0f;
        #pragma unroll
        for (int j = 0; j < 8; j++) { float x = ys[r * 64 + p * 8 + j]; sum += x * x; }
        sum += __shfl_xor_sync(~0u, sum, 1);
        sum += __shfl_xor_sync(~0u, sum, 2);
        sum += __shfl_xor_sync(~0u, sum, 4);
        if (p == 0) rs[r] = rsqrtf(sum * (1.0f / 64.0f) + 1e-6f);
    }
    __syncthreads();
    for (int i = tid; i < 2048; i += 256)
        ys[i] = ys[i] * rs[i >> 6] * nws[i & 63];
    __syncthreads();

    const int tn = tid & 31;
    const int tm = tid >> 5;
    float acc[4][4];
    #pragma unroll
    for (int i = 0; i < 4; i++)
        #pragma unroll
        for (int j = 0; j < 4; j++) acc[i][j] = 0.0f;

    #pragma unroll 8
    for (int vv = 0; vv < 64; vv++) {
        float b0 = wos[vv * 128 + tn];
        float b1 = wos[vv * 128 + tn + 32];
        float b2 = wos[vv * 128 + tn + 64];
        float b3 = wos[vv * 128 + tn + 96];
        #pragma unroll
        for (int i = 0; i < 4; i++) {
            float a = ys[(tm * 4 + i) * 64 + vv];
            acc[i][0] += a * b0; acc[i][1] += a * b1;
            acc[i][2] += a * b2; acc[i][3] += a * b3;
        }
    }
    #pragma unroll
    for (int i = 0; i < 4; i++) {
        size_t row = (size_t)(m0 + tm * 4 + i) * 2048 + n0 + tn;
        #pragma unroll
        for (int j = 0; j < 4; j++) out[row + 32 * j] = acc[i][j];
    }
}

// =====================================================================
extern "C" void kernel_launch(void* const* d_in, const int* in_sizes, int n_in,
                              void* d_out, int out_size)
{
    const float* x      = (const float*)d_in[0];
    const float* Wk     = (const float*)d_in[1];
    const float* Wv     = (const float*)d_in[2];
    const float* Wq     = (const float*)d_in[3];
    const float* Wa_w   = (const float*)d_in[4];
    const float* Wa_b   = (const float*)d_in[5];
    const float* lam    = (const float*)d_in[6];
    const float* norm_w = (const float*)d_in[7];
    const float* Wo     = (const float*)d_in[8];
    float* out = (float*)d_out;

    proj_gemm<<<dim3(128, 4), 256>>>(x, Wk, Wv, Wq, Wa_w);
    prep_kernel<<<1024, 256>>>(Wa_b, lam);
    ghc_kernel<<<1024, 256>>>();
    scan_kernel<<<4, 288>>>();
    out_gemm<<<dim3(16, 256), 256>>>(norm_w, Wo, out);
}